// round 15
// baseline (speedup 1.0000x reference)
// ColdDiffusion q_sample with anchor matching — Round 11.
// R10-validated bit-exact core (MUL2 / asc-k FFMA2 / ADD2, exact -2 anchor
// prescale; deferred even/odd tie resolution; acq_rel ticket fused blend).
// NEW: PPT=4 (xa..xd) at TPB=128 so each anchor-pair LDS feeds 4 points
// (LDS/cell and issue/cell halve; fma work invariant); CHUNK=1024/NCHUNK=8
// (grid 512 ~= one wave at 5 CTAs/SM via __launch_bounds__(128,5)).
#include <cuda_runtime.h>

#define D        8
#define M_ANCH   8192
#define BQ       16
#define NQ       2048
#define P_TOTAL  (BQ * NQ)          // 32768 points
#define CHUNK    1024               // anchors per CTA chunk
#define NCHUNK   (M_ANCH / CHUNK)   // 8
#define PAIRS    (CHUNK / 2)        // 512 anchor pairs
#define TPB      128                // threads per CTA
#define PPT      4                  // points per thread
#define PPC      (TPB * PPT)        // 512 points per CTA
#define NPG      (P_TOTAL / PPC)    // 64 point groups
#define FLT_BIG  3.402823466e38f

typedef unsigned long long u64;

// Per-point best ~((sortable_score<<32)|idx); MAX == reference argmin with
// first-index ties. Identity 0 == static zero-init; blender resets to 0.
__device__ u64      g_best[P_TOTAL];
// Per-point arrival tickets (acq_rel); NCHUNK-th arriver blends, then resets.
__device__ unsigned g_done[P_TOTAL];

__device__ __forceinline__ u64 pack2(float lo, float hi) {
    u64 r; asm("mov.b64 %0, {%1,%2};" : "=l"(r) : "f"(lo), "f"(hi)); return r;
}
__device__ __forceinline__ void unpack2(u64 v, float& lo, float& hi) {
    asm("mov.b64 {%0,%1}, %2;" : "=f"(lo), "=f"(hi) : "l"(v));
}
// Packed fp32x2 ops — per-half round-to-nearest, bitwise identical to scalar.
__device__ __forceinline__ u64 fma2(u64 a, u64 b, u64 c) {
    u64 d; asm("fma.rn.f32x2 %0, %1, %2, %3;" : "=l"(d) : "l"(a), "l"(b), "l"(c)); return d;
}
__device__ __forceinline__ u64 mul2(u64 a, u64 b) {
    u64 d; asm("mul.rn.f32x2 %0, %1, %2;" : "=l"(d) : "l"(a), "l"(b)); return d;
}
__device__ __forceinline__ u64 add2(u64 a, u64 b) {
    u64 d; asm("add.rn.f32x2 %0, %1, %2;" : "=l"(d) : "l"(a), "l"(b)); return d;
}
// Monotone float -> uint map (total order preserved; no NaNs in this data).
__device__ __forceinline__ unsigned sortable(float f) {
    unsigned u = __float_as_uint(f);
    return (u & 0x80000000u) ? ~u : (u | 0x80000000u);
}
// Ticket: release our prior fold, acquire all folds when we're last (same addr).
__device__ __forceinline__ unsigned ticket_acq_rel(unsigned* a) {
    unsigned r;
    asm volatile("atom.acq_rel.gpu.global.add.u32 %0, [%1], 1;"
                 : "=r"(r) : "l"(a) : "memory");
    return r;
}

// Recompute one pair's packed score (bit-identical chain) — even/odd resolve.
__device__ __forceinline__ u64 pair_score(const u64* __restrict__ s_pair,
                                          const u64* __restrict__ s_norm,
                                          const u64* xx, int p) {
    const ulonglong2* q = (const ulonglong2*)&s_pair[p * D];
    ulonglong2 q0 = q[0], q1 = q[1], q2 = q[2], q3 = q[3];
    u64 acc = mul2(xx[0], q0.x);
    acc = fma2(xx[1], q0.y, acc);
    acc = fma2(xx[2], q1.x, acc);
    acc = fma2(xx[3], q1.y, acc);
    acc = fma2(xx[4], q2.x, acc);
    acc = fma2(xx[5], q2.y, acc);
    acc = fma2(xx[6], q3.x, acc);
    acc = fma2(xx[7], q3.y, acc);
    return add2(acc, s_norm[p]);
}

// Blend epilogue for one finished point (reference rounding order).
__device__ __forceinline__ void blend_point(int point,
                                            const float* __restrict__ x,
                                            const float* __restrict__ anchors,
                                            const float* __restrict__ sa_tab,
                                            const float* __restrict__ sb_tab,
                                            const int* __restrict__ t,
                                            float* __restrict__ out) {
    u64 key = atomicExch(&g_best[point], 0ull);        // read final + reset
    g_done[point] = 0u;                                // reset ticket for replay
    const int bidx = (int)(unsigned)(~key & 0xFFFFFFFFull);

    const int tb = t[point / NQ];
    const float sa = sa_tab[tb];
    const float sb = sb_tab[tb];

    const float4* xp = (const float4*)(x + (size_t)point * D);
    const float4* ap = (const float4*)(anchors + (size_t)bidx * D);
    float4 x0 = xp[0], x1 = xp[1];
    float4 a0 = ap[0], a1 = ap[1];
    float4 o0, o1;
    // out = round(sa*x) + round(sb*a), no FMA contraction (reference order)
    o0.x = __fadd_rn(__fmul_rn(sa, x0.x), __fmul_rn(sb, a0.x));
    o0.y = __fadd_rn(__fmul_rn(sa, x0.y), __fmul_rn(sb, a0.y));
    o0.z = __fadd_rn(__fmul_rn(sa, x0.z), __fmul_rn(sb, a0.z));
    o0.w = __fadd_rn(__fmul_rn(sa, x0.w), __fmul_rn(sb, a0.w));
    o1.x = __fadd_rn(__fmul_rn(sa, x1.x), __fmul_rn(sb, a1.x));
    o1.y = __fadd_rn(__fmul_rn(sa, x1.y), __fmul_rn(sb, a1.y));
    o1.z = __fadd_rn(__fmul_rn(sa, x1.z), __fmul_rn(sb, a1.z));
    o1.w = __fadd_rn(__fmul_rn(sa, x1.w), __fmul_rn(sb, a1.w));

    float4* op = (float4*)(out + (size_t)point * D);
    op[0] = o0; op[1] = o1;
}

__device__ __forceinline__ void load_x(const float* __restrict__ x, int point, u64* xx) {
    const float4* xp = (const float4*)(x + (size_t)point * D);
    float4 v0 = xp[0], v1 = xp[1];
    xx[0] = pack2(v0.x, v0.x); xx[1] = pack2(v0.y, v0.y);
    xx[2] = pack2(v0.z, v0.z); xx[3] = pack2(v0.w, v0.w);
    xx[4] = pack2(v1.x, v1.x); xx[5] = pack2(v1.y, v1.y);
    xx[6] = pack2(v1.z, v1.z); xx[7] = pack2(v1.w, v1.w);
}

__global__ __launch_bounds__(TPB, 5) void scan_kernel(const float* __restrict__ x,
                                                      const float* __restrict__ anchors,
                                                      const float* __restrict__ sa_tab,
                                                      const float* __restrict__ sb_tab,
                                                      const int* __restrict__ t,
                                                      float* __restrict__ out) {
    // s_pair[p*8+k] = (-2*a[2p][k], -2*a[2p+1][k])  (pair-interleaved, k-major)
    __shared__ __align__(16) u64 s_pair[PAIRS * D];   // 32 KB
    __shared__ __align__(16) u64 s_norm[PAIRS];       // 4 KB (UNSCALED norms)

    const int tid   = threadIdx.x;
    const int pg    = blockIdx.x % NPG;
    const int ch    = blockIdx.x / NPG;
    const int abase = ch * CHUNK;

    // ---- pack this chunk's anchors (pre-scaled by -2, exact) into SMEM ----
    const float* A = anchors + (size_t)abase * D;
    for (int i = tid; i < CHUNK * D; i += TPB) {
        int j = i >> 3, k = i & 7;
        ((float*)&s_pair[(j >> 1) * D + k])[j & 1] = __fmul_rn(-2.0f, A[i]);
    }
    // norms from the ORIGINAL anchors: sequential sum of rounded squares
    for (int j = tid; j < CHUNK; j += TPB) {
        const float* a = A + j * D;
        float n = __fmul_rn(a[0], a[0]);
        #pragma unroll
        for (int k = 1; k < D; k++) n = __fadd_rn(n, __fmul_rn(a[k], a[k]));
        ((float*)&s_norm[j >> 1])[j & 1] = n;
    }
    __syncthreads();

    // ---- four points per thread ----
    const int point0 = pg * PPC + tid;
    const int point1 = point0 + TPB;
    const int point2 = point0 + 2 * TPB;
    const int point3 = point0 + 3 * TPB;
    u64 xa[D], xb[D], xc[D], xd[D];
    load_x(x, point0, xa);
    load_x(x, point1, xb);
    load_x(x, point2, xc);
    load_x(x, point3, xd);

    float bestA = FLT_BIG, bestB = FLT_BIG, bestC = FLT_BIG, bestD = FLT_BIG;
    int   bpA   = 0,       bpB   = 0,       bpC   = 0,       bpD   = 0;

    #pragma unroll 2
    for (int p = 0; p < PAIRS; p++) {
        const ulonglong2* q = (const ulonglong2*)&s_pair[p * D];
        ulonglong2 q0 = q[0], q1 = q[1], q2 = q[2], q3 = q[3];
        u64 nrm = s_norm[p];

        // dot' = sum_k x_k * (-2*a_k): exact pow2 scale commutes with every
        // rounding => chain reproduces -2*dot bitwise. MUL2/ADD2 endpoints rt=2.
        u64 aA = mul2(xa[0], q0.x);
        u64 aB = mul2(xb[0], q0.x);
        u64 aC = mul2(xc[0], q0.x);
        u64 aD = mul2(xd[0], q0.x);
        aA = fma2(xa[1], q0.y, aA); aB = fma2(xb[1], q0.y, aB);
        aC = fma2(xc[1], q0.y, aC); aD = fma2(xd[1], q0.y, aD);
        aA = fma2(xa[2], q1.x, aA); aB = fma2(xb[2], q1.x, aB);
        aC = fma2(xc[2], q1.x, aC); aD = fma2(xd[2], q1.x, aD);
        aA = fma2(xa[3], q1.y, aA); aB = fma2(xb[3], q1.y, aB);
        aC = fma2(xc[3], q1.y, aC); aD = fma2(xd[3], q1.y, aD);
        aA = fma2(xa[4], q2.x, aA); aB = fma2(xb[4], q2.x, aB);
        aC = fma2(xc[4], q2.x, aC); aD = fma2(xd[4], q2.x, aD);
        aA = fma2(xa[5], q2.y, aA); aB = fma2(xb[5], q2.y, aB);
        aC = fma2(xc[5], q2.y, aC); aD = fma2(xd[5], q2.y, aD);
        aA = fma2(xa[6], q3.x, aA); aB = fma2(xb[6], q3.x, aB);
        aC = fma2(xc[6], q3.x, aC); aD = fma2(xd[6], q3.x, aD);
        aA = fma2(xa[7], q3.y, aA); aB = fma2(xb[7], q3.y, aB);
        aC = fma2(xc[7], q3.y, aC); aD = fma2(xd[7], q3.y, aD);
        aA = add2(aA, nrm); aB = add2(aB, nrm);
        aC = add2(aC, nrm); aD = add2(aD, nrm);

        // deferred tie resolution: track pair min + pair index only
        { float lo, hi; unpack2(aA, lo, hi); float m = fminf(lo, hi);
          if (m < bestA) { bestA = m; bpA = p; } }
        { float lo, hi; unpack2(aB, lo, hi); float m = fminf(lo, hi);
          if (m < bestB) { bestB = m; bpB = p; } }
        { float lo, hi; unpack2(aC, lo, hi); float m = fminf(lo, hi);
          if (m < bestC) { bestC = m; bpC = p; } }
        { float lo, hi; unpack2(aD, lo, hi); float m = fminf(lo, hi);
          if (m < bestD) { bestD = m; bpD = p; } }
    }

    // resolve even/odd half of each winning pair (bit-identical recompute;
    // even half wins ties == lower anchor index, matching reference)
    int idxA, idxB, idxC, idxD;
    { float lo, hi; unpack2(pair_score(s_pair, s_norm, xa, bpA), lo, hi);
      idxA = abase + 2 * bpA + ((hi < lo) ? 1 : 0); }
    { float lo, hi; unpack2(pair_score(s_pair, s_norm, xb, bpB), lo, hi);
      idxB = abase + 2 * bpB + ((hi < lo) ? 1 : 0); }
    { float lo, hi; unpack2(pair_score(s_pair, s_norm, xc, bpC), lo, hi);
      idxC = abase + 2 * bpC + ((hi < lo) ? 1 : 0); }
    { float lo, hi; unpack2(pair_score(s_pair, s_norm, xd, bpD), lo, hi);
      idxD = abase + 2 * bpD + ((hi < lo) ? 1 : 0); }

    // fold this chunk's winners into the global per-point best (max-identity 0)
    atomicMax(&g_best[point0], ~(((u64)sortable(bestA) << 32) | (unsigned)idxA));
    atomicMax(&g_best[point1], ~(((u64)sortable(bestB) << 32) | (unsigned)idxB));
    atomicMax(&g_best[point2], ~(((u64)sortable(bestC) << 32) | (unsigned)idxC));
    atomicMax(&g_best[point3], ~(((u64)sortable(bestD) << 32) | (unsigned)idxD));

    // ---- fused finalize: acq_rel ticket; NCHUNK-th arriver blends ----
    if (ticket_acq_rel(&g_done[point0]) == NCHUNK - 1)
        blend_point(point0, x, anchors, sa_tab, sb_tab, t, out);
    if (ticket_acq_rel(&g_done[point1]) == NCHUNK - 1)
        blend_point(point1, x, anchors, sa_tab, sb_tab, t, out);
    if (ticket_acq_rel(&g_done[point2]) == NCHUNK - 1)
        blend_point(point2, x, anchors, sa_tab, sb_tab, t, out);
    if (ticket_acq_rel(&g_done[point3]) == NCHUNK - 1)
        blend_point(point3, x, anchors, sa_tab, sb_tab, t, out);
}

extern "C" void kernel_launch(void* const* d_in, const int* in_sizes, int n_in,
                              void* d_out, int out_size) {
    const float* x       = (const float*)d_in[0];  // [16,2048,4,2]
    const float* anchors = (const float*)d_in[1];  // [8192,4,2]
    const float* sa_tab  = (const float*)d_in[2];  // [1000]
    const float* sb_tab  = (const float*)d_in[3];  // [1000]
    const int*   t       = (const int*)d_in[4];    // [16]
    float*       out     = (float*)d_out;          // [16,2048,4,2]

    scan_kernel<<<NPG * NCHUNK, TPB>>>(x, anchors, sa_tab, sb_tab, t, out);
}

// round 17
// speedup vs baseline: 1.1772x; 1.1772x over previous
// ColdDiffusion q_sample with anchor matching — Round 12.
// = R11 datapath (PPT=4: each anchor-pair LDS feeds 4 points; halved LDS and
//   issue per cell) with the R11 occupancy bug fixed: CHUNK=512 -> grid=1024
//   CTAs (~7 CTAs/SM of work; 5 resident via __launch_bounds__(128,5)).
// + norms loaded two pairs per LDS.128 (unroll-2 static pairing).
// Core chain / deferred tie resolution / key fold / ticket blend are
// byte-identical to the validated R10 kernel (bit-exact vs reference).
#include <cuda_runtime.h>

#define D        8
#define M_ANCH   8192
#define BQ       16
#define NQ       2048
#define P_TOTAL  (BQ * NQ)          // 32768 points
#define CHUNK    512                // anchors per CTA chunk
#define NCHUNK   (M_ANCH / CHUNK)   // 16
#define PAIRS    (CHUNK / 2)        // 256 anchor pairs
#define TPB      128                // threads per CTA
#define PPT      4                  // points per thread
#define PPC      (TPB * PPT)        // 512 points per CTA
#define NPG      (P_TOTAL / PPC)    // 64 point groups -> grid = 64*16 = 1024
#define FLT_BIG  3.402823466e38f

typedef unsigned long long u64;

// Per-point best ~((sortable_score<<32)|idx); MAX == reference argmin with
// first-index ties. Identity 0 == static zero-init; blender resets to 0.
__device__ u64      g_best[P_TOTAL];
// Per-point arrival tickets (acq_rel); NCHUNK-th arriver blends, then resets.
__device__ unsigned g_done[P_TOTAL];

__device__ __forceinline__ u64 pack2(float lo, float hi) {
    u64 r; asm("mov.b64 %0, {%1,%2};" : "=l"(r) : "f"(lo), "f"(hi)); return r;
}
__device__ __forceinline__ void unpack2(u64 v, float& lo, float& hi) {
    asm("mov.b64 {%0,%1}, %2;" : "=f"(lo), "=f"(hi) : "l"(v));
}
// Packed fp32x2 ops — per-half round-to-nearest, bitwise identical to scalar.
__device__ __forceinline__ u64 fma2(u64 a, u64 b, u64 c) {
    u64 d; asm("fma.rn.f32x2 %0, %1, %2, %3;" : "=l"(d) : "l"(a), "l"(b), "l"(c)); return d;
}
__device__ __forceinline__ u64 mul2(u64 a, u64 b) {
    u64 d; asm("mul.rn.f32x2 %0, %1, %2;" : "=l"(d) : "l"(a), "l"(b)); return d;
}
__device__ __forceinline__ u64 add2(u64 a, u64 b) {
    u64 d; asm("add.rn.f32x2 %0, %1, %2;" : "=l"(d) : "l"(a), "l"(b)); return d;
}
// Monotone float -> uint map (total order preserved; no NaNs in this data).
__device__ __forceinline__ unsigned sortable(float f) {
    unsigned u = __float_as_uint(f);
    return (u & 0x80000000u) ? ~u : (u | 0x80000000u);
}
// Ticket: release our prior fold, acquire all folds when we're last (same addr).
__device__ __forceinline__ unsigned ticket_acq_rel(unsigned* a) {
    unsigned r;
    asm volatile("atom.acq_rel.gpu.global.add.u32 %0, [%1], 1;"
                 : "=r"(r) : "l"(a) : "memory");
    return r;
}

// Recompute one pair's packed score (bit-identical chain) — even/odd resolve.
__device__ __forceinline__ u64 pair_score(const u64* __restrict__ s_pair,
                                          const u64* __restrict__ s_norm,
                                          const u64* xx, int p) {
    const ulonglong2* q = (const ulonglong2*)&s_pair[p * D];
    ulonglong2 q0 = q[0], q1 = q[1], q2 = q[2], q3 = q[3];
    u64 acc = mul2(xx[0], q0.x);
    acc = fma2(xx[1], q0.y, acc);
    acc = fma2(xx[2], q1.x, acc);
    acc = fma2(xx[3], q1.y, acc);
    acc = fma2(xx[4], q2.x, acc);
    acc = fma2(xx[5], q2.y, acc);
    acc = fma2(xx[6], q3.x, acc);
    acc = fma2(xx[7], q3.y, acc);
    return add2(acc, s_norm[p]);
}

// Blend epilogue for one finished point (reference rounding order).
__device__ __forceinline__ void blend_point(int point,
                                            const float* __restrict__ x,
                                            const float* __restrict__ anchors,
                                            const float* __restrict__ sa_tab,
                                            const float* __restrict__ sb_tab,
                                            const int* __restrict__ t,
                                            float* __restrict__ out) {
    u64 key = atomicExch(&g_best[point], 0ull);        // read final + reset
    g_done[point] = 0u;                                // reset ticket for replay
    const int bidx = (int)(unsigned)(~key & 0xFFFFFFFFull);

    const int tb = t[point / NQ];
    const float sa = sa_tab[tb];
    const float sb = sb_tab[tb];

    const float4* xp = (const float4*)(x + (size_t)point * D);
    const float4* ap = (const float4*)(anchors + (size_t)bidx * D);
    float4 x0 = xp[0], x1 = xp[1];
    float4 a0 = ap[0], a1 = ap[1];
    float4 o0, o1;
    // out = round(sa*x) + round(sb*a), no FMA contraction (reference order)
    o0.x = __fadd_rn(__fmul_rn(sa, x0.x), __fmul_rn(sb, a0.x));
    o0.y = __fadd_rn(__fmul_rn(sa, x0.y), __fmul_rn(sb, a0.y));
    o0.z = __fadd_rn(__fmul_rn(sa, x0.z), __fmul_rn(sb, a0.z));
    o0.w = __fadd_rn(__fmul_rn(sa, x0.w), __fmul_rn(sb, a0.w));
    o1.x = __fadd_rn(__fmul_rn(sa, x1.x), __fmul_rn(sb, a1.x));
    o1.y = __fadd_rn(__fmul_rn(sa, x1.y), __fmul_rn(sb, a1.y));
    o1.z = __fadd_rn(__fmul_rn(sa, x1.z), __fmul_rn(sb, a1.z));
    o1.w = __fadd_rn(__fmul_rn(sa, x1.w), __fmul_rn(sb, a1.w));

    float4* op = (float4*)(out + (size_t)point * D);
    op[0] = o0; op[1] = o1;
}

__device__ __forceinline__ void load_x(const float* __restrict__ x, int point, u64* xx) {
    const float4* xp = (const float4*)(x + (size_t)point * D);
    float4 v0 = xp[0], v1 = xp[1];
    xx[0] = pack2(v0.x, v0.x); xx[1] = pack2(v0.y, v0.y);
    xx[2] = pack2(v0.z, v0.z); xx[3] = pack2(v0.w, v0.w);
    xx[4] = pack2(v1.x, v1.x); xx[5] = pack2(v1.y, v1.y);
    xx[6] = pack2(v1.z, v1.z); xx[7] = pack2(v1.w, v1.w);
}

__global__ __launch_bounds__(TPB, 5) void scan_kernel(const float* __restrict__ x,
                                                      const float* __restrict__ anchors,
                                                      const float* __restrict__ sa_tab,
                                                      const float* __restrict__ sb_tab,
                                                      const int* __restrict__ t,
                                                      float* __restrict__ out) {
    // s_pair[p*8+k] = (-2*a[2p][k], -2*a[2p+1][k])  (pair-interleaved, k-major)
    __shared__ __align__(16) u64 s_pair[PAIRS * D];   // 16 KB
    __shared__ __align__(16) u64 s_norm[PAIRS];       // 2 KB (UNSCALED norms)

    const int tid   = threadIdx.x;
    const int pg    = blockIdx.x % NPG;
    const int ch    = blockIdx.x / NPG;
    const int abase = ch * CHUNK;

    // ---- pack this chunk's anchors (pre-scaled by -2, exact) into SMEM ----
    const float* A = anchors + (size_t)abase * D;
    for (int i = tid; i < CHUNK * D; i += TPB) {
        int j = i >> 3, k = i & 7;
        ((float*)&s_pair[(j >> 1) * D + k])[j & 1] = __fmul_rn(-2.0f, A[i]);
    }
    // norms from the ORIGINAL anchors: sequential sum of rounded squares
    for (int j = tid; j < CHUNK; j += TPB) {
        const float* a = A + j * D;
        float n = __fmul_rn(a[0], a[0]);
        #pragma unroll
        for (int k = 1; k < D; k++) n = __fadd_rn(n, __fmul_rn(a[k], a[k]));
        ((float*)&s_norm[j >> 1])[j & 1] = n;
    }
    __syncthreads();

    // ---- four points per thread ----
    const int point0 = pg * PPC + tid;
    const int point1 = point0 + TPB;
    const int point2 = point0 + 2 * TPB;
    const int point3 = point0 + 3 * TPB;
    u64 xa[D], xb[D], xc[D], xd[D];
    load_x(x, point0, xa);
    load_x(x, point1, xb);
    load_x(x, point2, xc);
    load_x(x, point3, xd);

    float bestA = FLT_BIG, bestB = FLT_BIG, bestC = FLT_BIG, bestD = FLT_BIG;
    int   bpA   = 0,       bpB   = 0,       bpC   = 0,       bpD   = 0;

    // unroll 2 with a shared norm-pair load (one LDS.128 per two iterations)
    for (int p = 0; p < PAIRS; p += 2) {
        const ulonglong2 npair = *(const ulonglong2*)&s_norm[p];

        #pragma unroll
        for (int u = 0; u < 2; u++) {
            const int pp = p + u;
            const ulonglong2* q = (const ulonglong2*)&s_pair[pp * D];
            ulonglong2 q0 = q[0], q1 = q[1], q2 = q[2], q3 = q[3];
            const u64 nrm = u ? npair.y : npair.x;

            // dot' = sum_k x_k * (-2*a_k): exact pow2 scale commutes with all
            // roundings => chain reproduces -2*dot bitwise. MUL2/ADD2 rt=2.
            u64 aA = mul2(xa[0], q0.x);
            u64 aB = mul2(xb[0], q0.x);
            u64 aC = mul2(xc[0], q0.x);
            u64 aD = mul2(xd[0], q0.x);
            aA = fma2(xa[1], q0.y, aA); aB = fma2(xb[1], q0.y, aB);
            aC = fma2(xc[1], q0.y, aC); aD = fma2(xd[1], q0.y, aD);
            aA = fma2(xa[2], q1.x, aA); aB = fma2(xb[2], q1.x, aB);
            aC = fma2(xc[2], q1.x, aC); aD = fma2(xd[2], q1.x, aD);
            aA = fma2(xa[3], q1.y, aA); aB = fma2(xb[3], q1.y, aB);
            aC = fma2(xc[3], q1.y, aC); aD = fma2(xd[3], q1.y, aD);
            aA = fma2(xa[4], q2.x, aA); aB = fma2(xb[4], q2.x, aB);
            aC = fma2(xc[4], q2.x, aC); aD = fma2(xd[4], q2.x, aD);
            aA = fma2(xa[5], q2.y, aA); aB = fma2(xb[5], q2.y, aB);
            aC = fma2(xc[5], q2.y, aC); aD = fma2(xd[5], q2.y, aD);
            aA = fma2(xa[6], q3.x, aA); aB = fma2(xb[6], q3.x, aB);
            aC = fma2(xc[6], q3.x, aC); aD = fma2(xd[6], q3.x, aD);
            aA = fma2(xa[7], q3.y, aA); aB = fma2(xb[7], q3.y, aB);
            aC = fma2(xc[7], q3.y, aC); aD = fma2(xd[7], q3.y, aD);
            aA = add2(aA, nrm); aB = add2(aB, nrm);
            aC = add2(aC, nrm); aD = add2(aD, nrm);

            // deferred tie resolution: track pair min + pair index only
            { float lo, hi; unpack2(aA, lo, hi); float m = fminf(lo, hi);
              if (m < bestA) { bestA = m; bpA = pp; } }
            { float lo, hi; unpack2(aB, lo, hi); float m = fminf(lo, hi);
              if (m < bestB) { bestB = m; bpB = pp; } }
            { float lo, hi; unpack2(aC, lo, hi); float m = fminf(lo, hi);
              if (m < bestC) { bestC = m; bpC = pp; } }
            { float lo, hi; unpack2(aD, lo, hi); float m = fminf(lo, hi);
              if (m < bestD) { bestD = m; bpD = pp; } }
        }
    }

    // resolve even/odd half of each winning pair (bit-identical recompute;
    // even half wins ties == lower anchor index, matching reference)
    int idxA, idxB, idxC, idxD;
    { float lo, hi; unpack2(pair_score(s_pair, s_norm, xa, bpA), lo, hi);
      idxA = abase + 2 * bpA + ((hi < lo) ? 1 : 0); }
    { float lo, hi; unpack2(pair_score(s_pair, s_norm, xb, bpB), lo, hi);
      idxB = abase + 2 * bpB + ((hi < lo) ? 1 : 0); }
    { float lo, hi; unpack2(pair_score(s_pair, s_norm, xc, bpC), lo, hi);
      idxC = abase + 2 * bpC + ((hi < lo) ? 1 : 0); }
    { float lo, hi; unpack2(pair_score(s_pair, s_norm, xd, bpD), lo, hi);
      idxD = abase + 2 * bpD + ((hi < lo) ? 1 : 0); }

    // fold this chunk's winners into the global per-point best (max-identity 0)
    atomicMax(&g_best[point0], ~(((u64)sortable(bestA) << 32) | (unsigned)idxA));
    atomicMax(&g_best[point1], ~(((u64)sortable(bestB) << 32) | (unsigned)idxB));
    atomicMax(&g_best[point2], ~(((u64)sortable(bestC) << 32) | (unsigned)idxC));
    atomicMax(&g_best[point3], ~(((u64)sortable(bestD) << 32) | (unsigned)idxD));

    // ---- fused finalize: acq_rel ticket; NCHUNK-th arriver blends ----
    if (ticket_acq_rel(&g_done[point0]) == NCHUNK - 1)
        blend_point(point0, x, anchors, sa_tab, sb_tab, t, out);
    if (ticket_acq_rel(&g_done[point1]) == NCHUNK - 1)
        blend_point(point1, x, anchors, sa_tab, sb_tab, t, out);
    if (ticket_acq_rel(&g_done[point2]) == NCHUNK - 1)
        blend_point(point2, x, anchors, sa_tab, sb_tab, t, out);
    if (ticket_acq_rel(&g_done[point3]) == NCHUNK - 1)
        blend_point(point3, x, anchors, sa_tab, sb_tab, t, out);
}

extern "C" void kernel_launch(void* const* d_in, const int* in_sizes, int n_in,
                              void* d_out, int out_size) {
    const float* x       = (const float*)d_in[0];  // [16,2048,4,2]
    const float* anchors = (const float*)d_in[1];  // [8192,4,2]
    const float* sa_tab  = (const float*)d_in[2];  // [1000]
    const float* sb_tab  = (const float*)d_in[3];  // [1000]
    const int*   t       = (const int*)d_in[4];    // [16]
    float*       out     = (float*)d_out;          // [16,2048,4,2]

    scan_kernel<<<NPG * NCHUNK, TPB>>>(x, anchors, sa_tab, sb_tab, t, out);
}